// round 5
// baseline (speedup 1.0000x reference)
#include <cuda_runtime.h>
#include <cuda_bf16.h>
#include <cstdint>

// ============================================================================
// VersorLinear == one 8192x8192x8192 GEMM with a signed/permuted weight:
//   out[bs, o*32+k] = sum_{i,l} x[bs, i*32+l] * sign(k^l, l) * weight[o,i,k^l]
// followed by per-(bs,o) manifold normalization over the 32 components.
//
// mma.sync.m16n8k16 bf16 (HMMA) GEMM, 3-term bf16 split (xh*Wh + xh*Wl + xl*Wh)
// with fp32 accumulate for < 1e-4 relative error.
// R4 fix: B-fragment ldmatrix must be NON-trans for n-major smem tiles.
// ============================================================================

static constexpr int MDIM = 8192;   // B*S
static constexpr int NDIM = 8192;   // OUT_F*32
static constexpr int KDIM = 8192;   // IN_F*32
static constexpr int IFEA = 256;

// ---- static device scratch (1024-aligned for 16B vector access) ----
__device__ __align__(1024) float g_sign[1024];
__device__ __align__(1024) __nv_bfloat16 g_Xh[(size_t)MDIM * KDIM];
__device__ __align__(1024) __nv_bfloat16 g_Xl[(size_t)MDIM * KDIM];
__device__ __align__(1024) __nv_bfloat16 g_Wh[(size_t)NDIM * KDIM];
__device__ __align__(1024) __nv_bfloat16 g_Wl[(size_t)NDIM * KDIM];

// ============================ PTX helpers ===================================
__device__ __forceinline__ uint32_t smem_u32(const void* p) {
    uint32_t a;
    asm("{ .reg .u64 t; cvta.to.shared.u64 t, %1; cvt.u32.u64 %0, t; }"
        : "=r"(a) : "l"(p));
    return a;
}

__device__ __forceinline__ void cp16(uint32_t sdst, const void* gsrc) {
    asm volatile("cp.async.cg.shared.global [%0], [%1], 16;"
                 :: "r"(sdst), "l"(gsrc));
}

__device__ __forceinline__ void ldsm_x4(uint32_t* r, uint32_t addr) {
    asm volatile("ldmatrix.sync.aligned.m8n8.x4.shared.b16 {%0,%1,%2,%3}, [%4];"
                 : "=r"(r[0]), "=r"(r[1]), "=r"(r[2]), "=r"(r[3]) : "r"(addr));
}

__device__ __forceinline__ void ldsm_x2(uint32_t* r, uint32_t addr) {
    asm volatile("ldmatrix.sync.aligned.m8n8.x2.shared.b16 {%0,%1}, [%2];"
                 : "=r"(r[0]), "=r"(r[1]) : "r"(addr));
}

__device__ __forceinline__ void mma16816(float* c, const uint32_t* a, const uint32_t* b) {
    asm volatile(
        "mma.sync.aligned.m16n8k16.row.col.f32.bf16.bf16.f32 "
        "{%0,%1,%2,%3}, {%4,%5,%6,%7}, {%8,%9}, {%0,%1,%2,%3};"
        : "+f"(c[0]), "+f"(c[1]), "+f"(c[2]), "+f"(c[3])
        : "r"(a[0]), "r"(a[1]), "r"(a[2]), "r"(a[3]), "r"(b[0]), "r"(b[1]));
}

// ============================ builder kernels ===============================
// Cl(4,1) geometric-product sign: sign of e_a * e_b (result blade = a^b)
__global__ void init_sign_k() {
    int a = threadIdx.x;   // left blade
    int b = threadIdx.y;   // right blade
    float s = 1.f;
    int bits = a;
    for (int i = 0; i < 5; i++) {
        if ((b >> i) & 1) {
            for (int j = i + 1; j < 5; j++)
                if ((bits >> j) & 1) s = -s;
            if ((bits >> i) & 1) {
                if (i == 4) s = -s;   // e5^2 = -1
                bits &= ~(1 << i);
            } else {
                bits |= (1 << i);
            }
        }
    }
    g_sign[a * 32 + b] = s;
}

__global__ void cvt_x_k(const float* __restrict__ x) {
    size_t i = (size_t)blockIdx.x * blockDim.x + threadIdx.x;
    float v = x[i];
    __nv_bfloat16 h = __float2bfloat16(v);
    g_Xh[i] = h;
    g_Xl[i] = __float2bfloat16(v - __bfloat162float(h));
}

__global__ void build_w_k(const float* __restrict__ w) {
    size_t idx = (size_t)blockIdx.x * blockDim.x + threadIdx.x;
    int q = (int)(idx & 8191);     // (i,l)
    int n = (int)(idx >> 13);      // (o,k)
    int l = q & 31, i = q >> 5;
    int k = n & 31, o = n >> 5;
    int j = k ^ l;
    float v = g_sign[j * 32 + l] * w[((size_t)(o * IFEA + i) << 5) + j];
    __nv_bfloat16 h = __float2bfloat16(v);
    g_Wh[idx] = h;
    g_Wl[idx] = __float2bfloat16(v - __bfloat162float(h));
}

// ====================== normalization (separate epilogue) ===================
__global__ void __launch_bounds__(256) normalize_k(float* __restrict__ out) {
    __shared__ float sm[256 * 33];
    const size_t base = (size_t)blockIdx.x * (256 * 32);
    const int tid = threadIdx.x;

    #pragma unroll
    for (int e = tid; e < 256 * 32; e += 256) {
        const int v = e >> 5, c = e & 31;
        sm[v * 33 + c] = out[base + e];
    }
    __syncthreads();

    float a[32];
    float nsq = 0.f, l2sq = 0.f;
    #pragma unroll
    for (int k = 0; k < 32; k++) {
        a[k] = sm[tid * 33 + k];
        const float sq = a[k] * a[k];
        l2sq += sq;
        const int gg = __popc(k);
        const int neg = ((k >> 4) & 1) ^ ((gg * (gg - 1) / 2) & 1);
        nsq += neg ? -sq : sq;
    }
    float denom = fmaxf(sqrtf(fabsf(nsq) + 1e-6f), sqrtf(l2sq) * 0.25f + 1e-6f);
    denom = fmaxf(denom, 1.0f);
    const float inv = 1.0f / denom;
    #pragma unroll
    for (int k = 0; k < 32; k++) sm[tid * 33 + k] = a[k] * inv;
    __syncthreads();

    #pragma unroll
    for (int e = tid; e < 256 * 32; e += 256) {
        const int v = e >> 5, c = e & 31;
        out[base + e] = sm[v * 33 + c];
    }
}

// ============================== GEMM (mma.sync) =============================
// BM=128, BN=128, BK=32. 256 threads = 8 warps in 2(m) x 4(n); warp tile 64x32.
// smem: per stage 4 tiles (Ah, Al, Bh, Bl), each 128 rows x 64B padded to 80B.
// Double-buffered with cp.async.
static constexpr int ROWB   = 80;                 // padded row stride (bytes)
static constexpr int TILE_B = 128 * ROWB;         // 10240 B per tile
static constexpr int STG_B  = 4 * TILE_B;         // 40960 B per stage
static constexpr int SMEM_BYTES = 2 * STG_B;      // 81920 B

__global__ void __launch_bounds__(256, 2) versor_mma(float* __restrict__ out) {
    extern __shared__ __align__(128) char smem[];
    const uint32_t sb = smem_u32(smem);
    const int tid  = threadIdx.x;
    const int lane = tid & 31;
    const int warp = tid >> 5;
    const int wm = warp >> 2;          // 0..1 : 64-row slab
    const int wn = warp & 3;           // 0..3 : 32-col slab

    // grouped raster (GROUP_M = 8) for L2 reuse over the 64x64 tile grid
    const int pid = blockIdx.x;
    const int grp = pid >> 9;
    const int rem = pid & 511;
    const int pm  = (grp << 3) + (rem & 7);
    const int pn  = rem >> 3;
    const int bm  = pm * 128;
    const int bn  = pn * 128;

    const char* src0 = (const char*)(g_Xh + (size_t)bm * KDIM);
    const char* src1 = (const char*)(g_Xl + (size_t)bm * KDIM);
    const char* src2 = (const char*)(g_Wh + (size_t)bn * KDIM);
    const char* src3 = (const char*)(g_Wl + (size_t)bn * KDIM);

    // per-thread fill coordinates: 2 chunks per tile, 4 tiles = 8 cp.async
    const int r0 = tid >> 2;                 // rows 0..63   (h=0)
    const int r1 = 64 + (tid >> 2);          // rows 64..127 (h=1)
    const int c0 = (tid & 3) << 4;           // 16B chunk in row

    float acc[4][4][4];
    #pragma unroll
    for (int a = 0; a < 4; a++)
        #pragma unroll
        for (int b = 0; b < 4; b++)
            #pragma unroll
            for (int c = 0; c < 4; c++) acc[a][b][c] = 0.f;

    auto fill = [&](int buf, int kbyte) {
        const uint32_t s = sb + buf * STG_B;
        const size_t o0 = (size_t)r0 * (KDIM * 2) + kbyte + c0;
        const size_t o1 = (size_t)r1 * (KDIM * 2) + kbyte + c0;
        const uint32_t d0 = r0 * ROWB + c0;
        const uint32_t d1 = r1 * ROWB + c0;
        cp16(s + 0 * TILE_B + d0, src0 + o0);
        cp16(s + 0 * TILE_B + d1, src0 + o1);
        cp16(s + 1 * TILE_B + d0, src1 + o0);
        cp16(s + 1 * TILE_B + d1, src1 + o1);
        cp16(s + 2 * TILE_B + d0, src2 + o0);
        cp16(s + 2 * TILE_B + d1, src2 + o1);
        cp16(s + 3 * TILE_B + d0, src3 + o0);
        cp16(s + 3 * TILE_B + d1, src3 + o1);
        asm volatile("cp.async.commit_group;" ::: "memory");
    };

    fill(0, 0);

    const int NS = KDIM / 32;   // 256 stages
    for (int s = 0; s < NS; s++) {
        if (s + 1 < NS) {
            fill((s + 1) & 1, (s + 1) * 64);
            asm volatile("cp.async.wait_group 1;" ::: "memory");
        } else {
            asm volatile("cp.async.wait_group 0;" ::: "memory");
        }
        __syncthreads();

        const uint32_t stg = sb + (s & 1) * STG_B;
        const uint32_t ahB = stg;
        const uint32_t alB = stg + TILE_B;
        const uint32_t bhB = stg + 2 * TILE_B;
        const uint32_t blB = stg + 3 * TILE_B;

        #pragma unroll
        for (int kk = 0; kk < 2; kk++) {
            const int kb = kk * 32;   // byte offset of this k16 chunk

            // B fragments: n-major smem rows, NON-trans ldmatrix ->
            // lane holds (n = lane/4, k-pair = (lane%4)*2) as MMA requires.
            // lanes 0-7 address n0-7 @ k0-7 (reg b0); lanes 8-15 @ k8-15 (b1).
            uint32_t bh[4][2], bl[4][2];
            #pragma unroll
            for (int ni = 0; ni < 4; ni++) {
                const uint32_t ra = (uint32_t)((wn * 32 + ni * 8 + (lane & 7)) * ROWB
                                               + kb + ((lane >> 3) & 1) * 16);
                ldsm_x2(bh[ni], bhB + ra);
                ldsm_x2(bl[ni], blB + ra);
            }

            #pragma unroll
            for (int mi = 0; mi < 4; mi++) {
                const uint32_t raA = (uint32_t)((wm * 64 + mi * 16 + (lane & 15)) * ROWB
                                                + kb + ((lane >> 4) & 1) * 16);
                uint32_t ah[4], al[4];
                ldsm_x4(ah, ahB + raA);
                ldsm_x4(al, alB + raA);
                #pragma unroll
                for (int ni = 0; ni < 4; ni++) {
                    mma16816(acc[mi][ni], ah, bh[ni]);
                    mma16816(acc[mi][ni], ah, bl[ni]);
                    mma16816(acc[mi][ni], al, bh[ni]);
                }
            }
        }
        __syncthreads();
    }

    // epilogue: raw fp32 result (normalization is a separate kernel)
    #pragma unroll
    for (int mi = 0; mi < 4; mi++) {
        #pragma unroll
        for (int ni = 0; ni < 4; ni++) {
            const int row = bm + wm * 64 + mi * 16 + (lane >> 2);
            const int col = bn + wn * 32 + ni * 8 + (lane & 3) * 2;
            float2* p0 = (float2*)(out + (size_t)row * NDIM + col);
            float2* p1 = (float2*)(out + (size_t)(row + 8) * NDIM + col);
            *p0 = make_float2(acc[mi][ni][0], acc[mi][ni][1]);
            *p1 = make_float2(acc[mi][ni][2], acc[mi][ni][3]);
        }
    }
}

// ============================== launch ======================================
extern "C" void kernel_launch(void* const* d_in, const int* in_sizes, int n_in,
                              void* d_out, int out_size) {
    (void)in_sizes; (void)n_in; (void)out_size;
    const float* x = (const float*)d_in[0];
    const float* w = (const float*)d_in[1];
    float* out = (float*)d_out;

    init_sign_k<<<1, dim3(32, 32)>>>();
    cvt_x_k<<<(int)(((size_t)MDIM * KDIM) / 256), 256>>>(x);
    build_w_k<<<(int)(((size_t)NDIM * KDIM) / 256), 256>>>(w);

    cudaFuncSetAttribute(versor_mma,
                         cudaFuncAttributeMaxDynamicSharedMemorySize, SMEM_BYTES);
    versor_mma<<<64 * 64, 256, SMEM_BYTES>>>(out);

    normalize_k<<<(int)(((size_t)MDIM * NDIM) / (256 * 32)), 256>>>(out);
}

// round 7
// speedup vs baseline: 1.0349x; 1.0349x over previous
#include <cuda_runtime.h>
#include <cuda_bf16.h>
#include <cstdint>

// ============================================================================
// VersorLinear == one 8192x8192x8192 GEMM with a signed/permuted weight:
//   out[bs, o*32+k] = sum_{i,l} x[bs, i*32+l] * sign(k^l, l) * weight[o,i,k^l]
// followed by per-(bs,o) manifold normalization over the 32 components.
//
// mma.sync.m16n8k16 bf16 (HMMA) GEMM, 3-term bf16 split (xh*Wh + xh*Wl + xl*Wh)
// with fp32 accumulate. R6: manifold normalization fused into the GEMM
// epilogue (warp owns one aligned 32-col group per row; quad shfl reduction),
// builders vectorized 4 elems/thread.
// ============================================================================

static constexpr int MDIM = 8192;   // B*S
static constexpr int NDIM = 8192;   // OUT_F*32
static constexpr int KDIM = 8192;   // IN_F*32
static constexpr int IFEA = 256;

// ---- static device scratch (1024-aligned for 16B vector access) ----
__device__ __align__(1024) float g_sign[1024];
__device__ __align__(1024) __nv_bfloat16 g_Xh[(size_t)MDIM * KDIM];
__device__ __align__(1024) __nv_bfloat16 g_Xl[(size_t)MDIM * KDIM];
__device__ __align__(1024) __nv_bfloat16 g_Wh[(size_t)NDIM * KDIM];
__device__ __align__(1024) __nv_bfloat16 g_Wl[(size_t)NDIM * KDIM];

// ============================ PTX helpers ===================================
__device__ __forceinline__ uint32_t smem_u32(const void* p) {
    uint32_t a;
    asm("{ .reg .u64 t; cvta.to.shared.u64 t, %1; cvt.u32.u64 %0, t; }"
        : "=r"(a) : "l"(p));
    return a;
}

__device__ __forceinline__ void cp16(uint32_t sdst, const void* gsrc) {
    asm volatile("cp.async.cg.shared.global [%0], [%1], 16;"
                 :: "r"(sdst), "l"(gsrc));
}

__device__ __forceinline__ void ldsm_x4(uint32_t* r, uint32_t addr) {
    asm volatile("ldmatrix.sync.aligned.m8n8.x4.shared.b16 {%0,%1,%2,%3}, [%4];"
                 : "=r"(r[0]), "=r"(r[1]), "=r"(r[2]), "=r"(r[3]) : "r"(addr));
}

__device__ __forceinline__ void ldsm_x2(uint32_t* r, uint32_t addr) {
    asm volatile("ldmatrix.sync.aligned.m8n8.x2.shared.b16 {%0,%1}, [%2];"
                 : "=r"(r[0]), "=r"(r[1]) : "r"(addr));
}

__device__ __forceinline__ void mma16816(float* c, const uint32_t* a, const uint32_t* b) {
    asm volatile(
        "mma.sync.aligned.m16n8k16.row.col.f32.bf16.bf16.f32 "
        "{%0,%1,%2,%3}, {%4,%5,%6,%7}, {%8,%9}, {%0,%1,%2,%3};"
        : "+f"(c[0]), "+f"(c[1]), "+f"(c[2]), "+f"(c[3])
        : "r"(a[0]), "r"(a[1]), "r"(a[2]), "r"(a[3]), "r"(b[0]), "r"(b[1]));
}

// metric signature factor for blade k: -1 if (e5 in k) xor (reversal-odd)
__device__ __forceinline__ float sig_of(int k) {
    const int g = __popc(k);
    const int neg = ((k >> 4) & 1) ^ ((g * (g - 1) / 2) & 1);
    return neg ? -1.f : 1.f;
}

// ============================ builder kernels ===============================
// Cl(4,1) geometric-product sign: sign of e_a * e_b (result blade = a^b)
__global__ void init_sign_k() {
    int a = threadIdx.x;   // left blade
    int b = threadIdx.y;   // right blade
    float s = 1.f;
    int bits = a;
    for (int i = 0; i < 5; i++) {
        if ((b >> i) & 1) {
            for (int j = i + 1; j < 5; j++)
                if ((bits >> j) & 1) s = -s;
            if ((bits >> i) & 1) {
                if (i == 4) s = -s;   // e5^2 = -1
                bits &= ~(1 << i);
            } else {
                bits |= (1 << i);
            }
        }
    }
    g_sign[a * 32 + b] = s;
}

// 4 elements per thread, vectorized load/store
__global__ void __launch_bounds__(256) cvt_x_k(const float* __restrict__ x) {
    const size_t i = ((size_t)blockIdx.x * blockDim.x + threadIdx.x) * 4;
    const float4 v = *(const float4*)(x + i);
    __nv_bfloat16 h0 = __float2bfloat16(v.x);
    __nv_bfloat16 h1 = __float2bfloat16(v.y);
    __nv_bfloat16 h2 = __float2bfloat16(v.z);
    __nv_bfloat16 h3 = __float2bfloat16(v.w);
    __nv_bfloat16 l0 = __float2bfloat16(v.x - __bfloat162float(h0));
    __nv_bfloat16 l1 = __float2bfloat16(v.y - __bfloat162float(h1));
    __nv_bfloat16 l2 = __float2bfloat16(v.z - __bfloat162float(h2));
    __nv_bfloat16 l3 = __float2bfloat16(v.w - __bfloat162float(h3));
    __nv_bfloat162 H01 = __halves2bfloat162(h0, h1);
    __nv_bfloat162 H23 = __halves2bfloat162(h2, h3);
    __nv_bfloat162 L01 = __halves2bfloat162(l0, l1);
    __nv_bfloat162 L23 = __halves2bfloat162(l2, l3);
    uint2 uh, ul;
    uh.x = *(uint32_t*)&H01; uh.y = *(uint32_t*)&H23;
    ul.x = *(uint32_t*)&L01; ul.y = *(uint32_t*)&L23;
    *(uint2*)(g_Xh + i) = uh;
    *(uint2*)(g_Xl + i) = ul;
}

// 4 consecutive (same n, same i, l0..l0+3) elements per thread
__global__ void __launch_bounds__(256) build_w_k(const float* __restrict__ w) {
    const size_t idx = ((size_t)blockIdx.x * blockDim.x + threadIdx.x) * 4;
    const int q = (int)(idx & 8191);     // (i,l)
    const int n = (int)(idx >> 13);      // (o,k)
    const int l0 = q & 31, i = q >> 5;
    const int k = n & 31, o = n >> 5;
    const float* wrow = w + ((size_t)(o * IFEA + i) << 5);

    __nv_bfloat16 h[4], lo[4];
    #pragma unroll
    for (int d = 0; d < 4; d++) {
        const int l = l0 + d;
        const int j = k ^ l;
        const float v = g_sign[j * 32 + l] * wrow[j];
        h[d] = __float2bfloat16(v);
        lo[d] = __float2bfloat16(v - __bfloat162float(h[d]));
    }
    __nv_bfloat162 H01 = __halves2bfloat162(h[0], h[1]);
    __nv_bfloat162 H23 = __halves2bfloat162(h[2], h[3]);
    __nv_bfloat162 L01 = __halves2bfloat162(lo[0], lo[1]);
    __nv_bfloat162 L23 = __halves2bfloat162(lo[2], lo[3]);
    uint2 uh, ul;
    uh.x = *(uint32_t*)&H01; uh.y = *(uint32_t*)&H23;
    ul.x = *(uint32_t*)&L01; ul.y = *(uint32_t*)&L23;
    *(uint2*)(g_Wh + idx) = uh;
    *(uint2*)(g_Wl + idx) = ul;
}

// ============================== GEMM (mma.sync) =============================
// BM=128, BN=128, BK=32. 256 threads = 8 warps in 2(m) x 4(n); warp tile 64x32.
// smem: per stage 4 tiles (Ah, Al, Bh, Bl), each 128 rows x 64B padded to 80B.
// Double-buffered with cp.async. Manifold normalization fused into epilogue.
static constexpr int ROWB   = 80;                 // padded row stride (bytes)
static constexpr int TILE_B = 128 * ROWB;         // 10240 B per tile
static constexpr int STG_B  = 4 * TILE_B;         // 40960 B per stage
static constexpr int SMEM_BYTES = 2 * STG_B;      // 81920 B

__global__ void __launch_bounds__(256, 2) versor_mma(float* __restrict__ out) {
    extern __shared__ __align__(128) char smem[];
    const uint32_t sb = smem_u32(smem);
    const int tid  = threadIdx.x;
    const int lane = tid & 31;
    const int warp = tid >> 5;
    const int wm = warp >> 2;          // 0..1 : 64-row slab
    const int wn = warp & 3;           // 0..3 : 32-col slab

    // grouped raster (GROUP_M = 8) for L2 reuse over the 64x64 tile grid
    const int pid = blockIdx.x;
    const int grp = pid >> 9;
    const int rem = pid & 511;
    const int pm  = (grp << 3) + (rem & 7);
    const int pn  = rem >> 3;
    const int bm  = pm * 128;
    const int bn  = pn * 128;

    const char* src0 = (const char*)(g_Xh + (size_t)bm * KDIM);
    const char* src1 = (const char*)(g_Xl + (size_t)bm * KDIM);
    const char* src2 = (const char*)(g_Wh + (size_t)bn * KDIM);
    const char* src3 = (const char*)(g_Wl + (size_t)bn * KDIM);

    // per-thread fill coordinates: 2 chunks per tile, 4 tiles = 8 cp.async
    const int r0 = tid >> 2;                 // rows 0..63   (h=0)
    const int r1 = 64 + (tid >> 2);          // rows 64..127 (h=1)
    const int c0 = (tid & 3) << 4;           // 16B chunk in row

    float acc[4][4][4];
    #pragma unroll
    for (int a = 0; a < 4; a++)
        #pragma unroll
        for (int b = 0; b < 4; b++)
            #pragma unroll
            for (int c = 0; c < 4; c++) acc[a][b][c] = 0.f;

    auto fill = [&](int buf, int kbyte) {
        const uint32_t s = sb + buf * STG_B;
        const size_t o0 = (size_t)r0 * (KDIM * 2) + kbyte + c0;
        const size_t o1 = (size_t)r1 * (KDIM * 2) + kbyte + c0;
        const uint32_t d0 = r0 * ROWB + c0;
        const uint32_t d1 = r1 * ROWB + c0;
        cp16(s + 0 * TILE_B + d0, src0 + o0);
        cp16(s + 0 * TILE_B + d1, src0 + o1);
        cp16(s + 1 * TILE_B + d0, src1 + o0);
        cp16(s + 1 * TILE_B + d1, src1 + o1);
        cp16(s + 2 * TILE_B + d0, src2 + o0);
        cp16(s + 2 * TILE_B + d1, src2 + o1);
        cp16(s + 3 * TILE_B + d0, src3 + o0);
        cp16(s + 3 * TILE_B + d1, src3 + o1);
        asm volatile("cp.async.commit_group;" ::: "memory");
    };

    fill(0, 0);

    const int NS = KDIM / 32;   // 256 stages
    for (int s = 0; s < NS; s++) {
        if (s + 1 < NS) {
            fill((s + 1) & 1, (s + 1) * 64);
            asm volatile("cp.async.wait_group 1;" ::: "memory");
        } else {
            asm volatile("cp.async.wait_group 0;" ::: "memory");
        }
        __syncthreads();

        const uint32_t stg = sb + (s & 1) * STG_B;
        const uint32_t ahB = stg;
        const uint32_t alB = stg + TILE_B;
        const uint32_t bhB = stg + 2 * TILE_B;
        const uint32_t blB = stg + 3 * TILE_B;

        #pragma unroll
        for (int kk = 0; kk < 2; kk++) {
            const int kb = kk * 32;   // byte offset of this k16 chunk

            // B fragments: n-major smem rows, NON-trans ldmatrix ->
            // lane holds (n = lane/4, k-pair = (lane%4)*2) as MMA requires.
            uint32_t bh[4][2], bl[4][2];
            #pragma unroll
            for (int ni = 0; ni < 4; ni++) {
                const uint32_t ra = (uint32_t)((wn * 32 + ni * 8 + (lane & 7)) * ROWB
                                               + kb + ((lane >> 3) & 1) * 16);
                ldsm_x2(bh[ni], bhB + ra);
                ldsm_x2(bl[ni], blB + ra);
            }

            #pragma unroll
            for (int mi = 0; mi < 4; mi++) {
                const uint32_t raA = (uint32_t)((wm * 64 + mi * 16 + (lane & 15)) * ROWB
                                                + kb + ((lane >> 4) & 1) * 16);
                uint32_t ah[4], al[4];
                ldsm_x4(ah, ahB + raA);
                ldsm_x4(al, alB + raA);
                #pragma unroll
                for (int ni = 0; ni < 4; ni++) {
                    mma16816(acc[mi][ni], ah, bh[ni]);
                    mma16816(acc[mi][ni], ah, bl[ni]);
                    mma16816(acc[mi][ni], al, bh[ni]);
                }
            }
        }
        __syncthreads();
    }

    // ---- fused epilogue: manifold normalization + store -------------------
    // Warp covers cols [bn + wn*32, +32) == exactly one 32-component group.
    // Lane holds, per row, cols ni*8 + (lane&3)*2 + {0,1}. The 4 lanes of a
    // quad (same lane>>2) jointly own a full row: butterfly-sum over the quad.
    float sg[4][2];
    #pragma unroll
    for (int ni = 0; ni < 4; ni++) {
        const int k0 = ni * 8 + (lane & 3) * 2;
        sg[ni][0] = sig_of(k0);
        sg[ni][1] = sig_of(k0 + 1);
    }

    #pragma unroll
    for (int mi = 0; mi < 4; mi++) {
        #pragma unroll
        for (int h = 0; h < 2; h++) {           // c-pair {0,1} -> row, {2,3} -> row+8
            float nsq = 0.f, l2sq = 0.f;
            #pragma unroll
            for (int ni = 0; ni < 4; ni++) {
                const float v0 = acc[mi][ni][2 * h + 0];
                const float v1 = acc[mi][ni][2 * h + 1];
                const float q0 = v0 * v0, q1 = v1 * v1;
                l2sq += q0 + q1;
                nsq  += sg[ni][0] * q0 + sg[ni][1] * q1;
            }
            nsq  += __shfl_xor_sync(0xFFFFFFFFu, nsq, 1);
            l2sq += __shfl_xor_sync(0xFFFFFFFFu, l2sq, 1);
            nsq  += __shfl_xor_sync(0xFFFFFFFFu, nsq, 2);
            l2sq += __shfl_xor_sync(0xFFFFFFFFu, l2sq, 2);

            float denom = fmaxf(sqrtf(fabsf(nsq) + 1e-6f),
                                sqrtf(l2sq) * 0.25f + 1e-6f);
            denom = fmaxf(denom, 1.0f);
            const float inv = 1.0f / denom;

            const int row = bm + wm * 64 + mi * 16 + h * 8 + (lane >> 2);
            float* orow = out + (size_t)row * NDIM + bn + wn * 32 + (lane & 3) * 2;
            #pragma unroll
            for (int ni = 0; ni < 4; ni++) {
                *(float2*)(orow + ni * 8) =
                    make_float2(acc[mi][ni][2 * h + 0] * inv,
                                acc[mi][ni][2 * h + 1] * inv);
            }
        }
    }
}

// ============================== launch ======================================
extern "C" void kernel_launch(void* const* d_in, const int* in_sizes, int n_in,
                              void* d_out, int out_size) {
    (void)in_sizes; (void)n_in; (void)out_size;
    const float* x = (const float*)d_in[0];
    const float* w = (const float*)d_in[1];
    float* out = (float*)d_out;

    init_sign_k<<<1, dim3(32, 32)>>>();
    cvt_x_k<<<(int)(((size_t)MDIM * KDIM) / 1024), 256>>>(x);
    build_w_k<<<(int)(((size_t)NDIM * KDIM) / 1024), 256>>>(w);

    cudaFuncSetAttribute(versor_mma,
                         cudaFuncAttributeMaxDynamicSharedMemorySize, SMEM_BYTES);
    versor_mma<<<64 * 64, 256, SMEM_BYTES>>>(out);
}